// round 10
// baseline (speedup 1.0000x reference)
#include <cuda_runtime.h>
#include <cuda_bf16.h>
#include <cstdint>

// token_reprs: [B=32, L=512, H=768] f32 ; pos_idx: [B,E=32,M=8,S=4] i32
// out f32: entity [B,E,H] @0 ; mentions [B,E,M,H] @786432 ; mask [B,E,M] @7077888

#define B_ 32
#define L_ 512
#define H_ 768
#define E_ 32
#define M_ 8
#define S_ 4
#define HV (H_ / 4)            // 192 float4 per token row
#define CF 16                  // floats per H-chunk handled by one block
#define NCH (H_ / CF)          // 48 chunks
#define RPAD 20                // padded row stride in floats (16B-aligned, bank-spread)
#define IDX_PER_B (E_ * M_ * S_)   // 1024

// Dense-stage kernel: instead of 100 MB of gathered global reads, each block
// streams ALL 512 rows of its 16-float chunk into smem (48 MB chip-wide, read
// exactly once, fully coalesced), then computes every mention/entity of the
// batch from smem. LTS traffic: 129 MB -> 76 MB. Thread = (entity, float-pair):
// entity sums stay thread-local; one barrier total.
__global__ __launch_bounds__(256, 5)
void entity_repr_kernel(const float* __restrict__ tok,
                        const int* __restrict__ pos,
                        float* __restrict__ ent,
                        float* __restrict__ men,
                        float* __restrict__ mask)
{
    __shared__ float rows[L_ * RPAD];   // [512][20] floats, data in [.][0..15]
    __shared__ int   sidx[IDX_PER_B];   // all indices of this batch

    const int bx = blockIdx.x;
    const int b  = bx / NCH;
    const int c  = bx % NCH;            // H-chunk: floats [c*16, c*16+16)
    const int t  = threadIdx.x;

    // Load all 1024 indices for the batch (4 per thread)
    #pragma unroll
    for (int i = 0; i < 4; i++)
        sidx[i * 256 + t] = pos[(size_t)b * IDX_PER_B + i * 256 + t];

    // Dense stage: 512 rows x 4 float4. linear = i*256+t; r=linear/4, j=linear%4.
    // Warp covers 8 rows x 64B contiguous segments -> all sectors fully used.
    {
        const float4* __restrict__ tokb =
            reinterpret_cast<const float4*>(tok) + (size_t)b * L_ * HV + c * 4;
        #pragma unroll
        for (int i = 0; i < 8; i++) {
            const int linear = i * 256 + t;
            const int r = linear >> 2;
            const int j = linear & 3;
            const float4 v = __ldg(&tokb[(size_t)r * HV + j]);
            // STS.128 at 80r+16j bytes: 16B aligned, conflict-free (20r+4j mod 32 distinct)
            *reinterpret_cast<float4*>(&rows[r * RPAD + j * 4]) = v;
        }
    }
    __syncthreads();

    // Compute: thread = (entity e = t/8, float-pair f2 = t%8) -> floats 2f2, 2f2+1
    const int e  = t >> 3;
    const int f2 = t & 7;
    const int fo = 2 * f2;              // float offset within chunk

    const int* I = sidx + e * (M_ * S_);

    float* __restrict__ men2 =
        men + ((size_t)(b * E_ + e) * M_) * H_ + c * CF + fo;
    float* __restrict__ ent2 =
        ent + (size_t)(b * E_ + e) * H_ + c * CF + fo;

    float ex = 0.f, ey = 0.f;

    #pragma unroll
    for (int m = 0; m < M_; m++) {
        const int r0 = I[m * S_ + 0];
        const int r1 = I[m * S_ + 1];
        const int r2 = I[m * S_ + 2];
        const int r3 = I[m * S_ + 3];

        const float2 v0 = *reinterpret_cast<const float2*>(&rows[r0 * RPAD + fo]);
        const float2 v1 = *reinterpret_cast<const float2*>(&rows[r1 * RPAD + fo]);
        const float2 v2 = *reinterpret_cast<const float2*>(&rows[r2 * RPAD + fo]);
        const float2 v3 = *reinterpret_cast<const float2*>(&rows[r3 * RPAD + fo]);

        float2 r;
        r.x = (v0.x + v1.x + v2.x + v3.x) * 0.25f;
        r.y = (v0.y + v1.y + v2.y + v3.y) * 0.25f;

        *reinterpret_cast<float2*>(&men2[(size_t)m * H_]) = r;

        ex += r.x; ey += r.y;
    }

    float2 er;
    er.x = ex * 0.125f;
    er.y = ey * 0.125f;
    *reinterpret_cast<float2*>(ent2) = er;

    // mask [B, E, M]: one chunk-0 block per batch writes its 256 values
    if (c == 0) {
        mask[(size_t)b * (E_ * M_) + t] = 1.0f;
    }
}

extern "C" void kernel_launch(void* const* d_in, const int* in_sizes, int n_in,
                              void* d_out, int out_size)
{
    const float* tok = (const float*)d_in[0];
    const int*   pos = (const int*)d_in[1];

    float* out = (float*)d_out;
    float* ent  = out;                                  // 786432
    float* men  = out + (size_t)B_ * E_ * H_;           // +786432
    float* mask = men + (size_t)B_ * E_ * M_ * H_;      // +6291456

    entity_repr_kernel<<<B_ * NCH, 256>>>(tok, pos, ent, men, mask);
}

// round 11
// speedup vs baseline: 1.5601x; 1.5601x over previous
#include <cuda_runtime.h>
#include <cuda_bf16.h>
#include <cstdint>

// token_reprs: [B=32, L=512, H=768] f32 ; pos_idx: [B,E=32,M=8,S=4] i32
// out f32: entity [B,E,H] @0 ; mentions [B,E,M,H] @786432 ; mask [B,E,M] @7077888

#define B_ 32
#define L_ 512
#define H_ 768
#define E_ 32
#define M_ 8
#define S_ 4
#define HV (H_ / 4)            // 192 float4 per token row
#define CF 32                  // floats per H-chunk (= 8 float4 = 128 B rows)
#define CV (CF / 4)            // 8 float4 per chunk row
#define NCH (H_ / CF)          // 24 chunks
#define IDX_PER_B (E_ * M_ * S_)   // 1024

// Dense-stage v2: block = (batch, 32-float chunk). Stage all 512 rows x 128B
// into smem with coalesced LDG.128/STS.128 (48 MB chip-wide, each byte read
// once), then gather from smem with LDS.128. Row stride = exactly 128B, and
// thread map t = e*8+col makes each quarter-warp phase read ONE row's 128B
// across all 32 banks -> conflict-free for arbitrary gather rows.
// LTS traffic: 129 MB (R2) -> 76 MB.
__global__ __launch_bounds__(256, 3)
void entity_repr_kernel(const float* __restrict__ tok,
                        const int* __restrict__ pos,
                        float* __restrict__ ent,
                        float* __restrict__ men,
                        float* __restrict__ mask)
{
    __shared__ float rows[L_ * CF];     // [512][32] floats, 128B rows, 64 KB
    __shared__ int   sidx[IDX_PER_B];   // all 1024 indices of this batch

    const int bx = blockIdx.x;
    const int b  = bx / NCH;
    const int c  = bx % NCH;            // floats [c*32, c*32+32)
    const int t  = threadIdx.x;

    // Indices: 4 per thread, coalesced
    #pragma unroll
    for (int i = 0; i < 4; i++)
        sidx[i * 256 + t] = pos[(size_t)b * IDX_PER_B + i * 256 + t];

    // Dense stage: 4096 float4 = 16 per thread. Warp covers 4 rows x 128B,
    // fully coalesced LDG.128; STS.128 phases are one-row 128B -> conflict-free.
    {
        const float4* __restrict__ tokb =
            reinterpret_cast<const float4*>(tok) + (size_t)b * L_ * HV + c * CV;
        float4* __restrict__ srow4 = reinterpret_cast<float4*>(rows);
        #pragma unroll
        for (int i = 0; i < 16; i++) {
            const int linear = i * 256 + t;     // 0..4095
            const int r = linear >> 3;          // row 0..511
            const int j = linear & 7;           // float4 col 0..7
            srow4[r * CV + j] = __ldg(&tokb[(size_t)r * HV + j]);
        }
    }
    __syncthreads();

    // Compute: thread = (entity e = t>>3, float4-col = t&7)
    const int e   = t >> 3;
    const int col = t & 7;

    const int* I = sidx + e * (M_ * S_);
    const float4* __restrict__ srow4 = reinterpret_cast<const float4*>(rows);

    float4* __restrict__ men4 =
        reinterpret_cast<float4*>(men) + ((size_t)(b * E_ + e) * M_) * HV + c * CV + col;
    float4* __restrict__ ent4 =
        reinterpret_cast<float4*>(ent) + (size_t)(b * E_ + e) * HV + c * CV + col;

    float ex = 0.f, ey = 0.f, ez = 0.f, ew = 0.f;

    #pragma unroll
    for (int m = 0; m < M_; m++) {
        const float4 v0 = srow4[I[m * S_ + 0] * CV + col];
        const float4 v1 = srow4[I[m * S_ + 1] * CV + col];
        const float4 v2 = srow4[I[m * S_ + 2] * CV + col];
        const float4 v3 = srow4[I[m * S_ + 3] * CV + col];

        float4 r;
        r.x = (v0.x + v1.x + v2.x + v3.x) * 0.25f;
        r.y = (v0.y + v1.y + v2.y + v3.y) * 0.25f;
        r.z = (v0.z + v1.z + v2.z + v3.z) * 0.25f;
        r.w = (v0.w + v1.w + v2.w + v3.w) * 0.25f;

        // Warp writes 4 entities x 128B contiguous segments
        men4[(size_t)m * HV] = r;

        ex += r.x; ey += r.y; ez += r.z; ew += r.w;
    }

    float4 er;
    er.x = ex * 0.125f; er.y = ey * 0.125f;
    er.z = ez * 0.125f; er.w = ew * 0.125f;
    ent4[0] = er;

    // mask [B, E, M]: one chunk-0 block per batch writes its 256 values
    if (c == 0) {
        mask[(size_t)b * (E_ * M_) + t] = 1.0f;
    }
}

extern "C" void kernel_launch(void* const* d_in, const int* in_sizes, int n_in,
                              void* d_out, int out_size)
{
    const float* tok = (const float*)d_in[0];
    const int*   pos = (const int*)d_in[1];

    float* out = (float*)d_out;
    float* ent  = out;                                  // 786432
    float* men  = out + (size_t)B_ * E_ * H_;           // +786432
    float* mask = men + (size_t)B_ * E_ * M_ * H_;      // +6291456

    entity_repr_kernel<<<B_ * NCH, 256>>>(tok, pos, ent, men, mask);
}

// round 12
// speedup vs baseline: 1.8221x; 1.1679x over previous
#include <cuda_runtime.h>
#include <cuda_bf16.h>
#include <cstdint>

// token_reprs: [B=32, L=512, H=768] f32 ; pos_idx: [B,E=32,M=8,S=4] i32
// out f32: entity [B,E,H] @0 ; mentions [B,E,M,H] @786432 ; mask [B,E,M] @7077888

#define B_ 32
#define L_ 512
#define H_ 768
#define E_ 32
#define M_ 8
#define S_ 4
#define HV (H_ / 4)          // 192 float4 per row

// R2 structure (best: LTS-bound at ~93% of cap) minus the index smem-stage +
// __syncthreads: indices come in as uniform int4 loads (same address across
// the block -> one L1 sector, broadcast), prefetched one mention ahead so
// index latency hides under the previous mention's gathers. No barriers at all.
__global__ __launch_bounds__(HV)
void entity_repr_kernel(const float* __restrict__ tok,
                        const int* __restrict__ pos,
                        float* __restrict__ ent,
                        float* __restrict__ men,
                        float* __restrict__ mask)
{
    const int be = blockIdx.x;          // 0 .. B*E-1
    const int b  = be >> 5;             // E_ == 32
    const int t  = threadIdx.x;         // float4 column index, 0..191

    // One int4 per mention: its 4 span indices. Uniform across the block.
    const int4* __restrict__ idx4 =
        reinterpret_cast<const int4*>(pos) + (size_t)be * M_;

    const float4* __restrict__ tokb =
        reinterpret_cast<const float4*>(tok) + (size_t)b * L_ * HV;

    float4* __restrict__ men4 =
        reinterpret_cast<float4*>(men) + ((size_t)be * M_) * HV;
    float4* __restrict__ ent4 =
        reinterpret_cast<float4*>(ent) + (size_t)be * HV;

    float ex = 0.f, ey = 0.f, ez = 0.f, ew = 0.f;

    int4 cur = __ldg(&idx4[0]);

    #pragma unroll
    for (int m = 0; m < M_; m++) {
        // Prefetch next mention's indices; L1-broadcast, hides under gathers.
        int4 nxt = cur;
        if (m + 1 < M_) nxt = __ldg(&idx4[m + 1]);

        const float4 v0 = tokb[(size_t)cur.x * HV + t];
        const float4 v1 = tokb[(size_t)cur.y * HV + t];
        const float4 v2 = tokb[(size_t)cur.z * HV + t];
        const float4 v3 = tokb[(size_t)cur.w * HV + t];

        float4 r;
        r.x = (v0.x + v1.x + v2.x + v3.x) * 0.25f;
        r.y = (v0.y + v1.y + v2.y + v3.y) * 0.25f;
        r.z = (v0.z + v1.z + v2.z + v3.z) * 0.25f;
        r.w = (v0.w + v1.w + v2.w + v3.w) * 0.25f;

        men4[(size_t)m * HV + t] = r;

        ex += r.x; ey += r.y; ez += r.z; ew += r.w;

        cur = nxt;
    }

    float4 er;
    er.x = ex * 0.125f; er.y = ey * 0.125f;
    er.z = ez * 0.125f; er.w = ew * 0.125f;
    ent4[t] = er;

    if (t < M_) {
        mask[(size_t)be * M_ + t] = 1.0f;
    }
}

extern "C" void kernel_launch(void* const* d_in, const int* in_sizes, int n_in,
                              void* d_out, int out_size)
{
    const float* tok = (const float*)d_in[0];
    const int*   pos = (const int*)d_in[1];

    float* out = (float*)d_out;
    float* ent  = out;                                  // 786432
    float* men  = out + (size_t)B_ * E_ * H_;           // +786432
    float* mask = men + (size_t)B_ * E_ * M_ * H_;      // +6291456

    entity_repr_kernel<<<B_ * E_, HV>>>(tok, pos, ent, men, mask);
}